// round 1
// baseline (speedup 1.0000x reference)
#include <cuda_runtime.h>

#define B_  2
#define C_  272
#define H_  128
#define W_  128
#define G_  17
#define CG_ 16
#define HW_ (H_*W_)

// ---------------- scratch (device globals; no allocation) ----------------
__device__ __align__(16) float g_xT[B_*G_*HW_*CG_];        // x transposed: (b,g,h,w,c16)
__device__ __align__(16) float g_off[B_*G_*18*HW_];        // offsets: (b,g, slot18, h, w)
__device__ __align__(16) float g_conv[B_*C_*HW_];          // deform-conv output (B,C,H,W)
__device__ float g_mean[C_];
__device__ float g_istd[C_];

// ---------------- K0: transpose x (B,C,H,W) -> (b,g,pos,c16) ----------------
__global__ void k_transpose(const float* __restrict__ x) {
    int t = blockIdx.x * blockDim.x + threadIdx.x;
    const int total = B_*G_*HW_*4;
    if (t >= total) return;
    int c4  = t & 3;
    int r   = t >> 2;              // bg*HW + pos
    int pos = r & (HW_ - 1);
    int bg  = r >> 14;             // HW_ = 2^14
    const float* src = x + (size_t)bg * CG_ * HW_ + pos;
    float4 v;
    v.x = src[(size_t)(c4*4+0)*HW_];
    v.y = src[(size_t)(c4*4+1)*HW_];
    v.z = src[(size_t)(c4*4+2)*HW_];
    v.w = src[(size_t)(c4*4+3)*HW_];
    reinterpret_cast<float4*>(g_xT)[(size_t)r*4 + c4] = v;
}

// ---------------- K1: offset-transform conv + affine->offset ----------------
// block: (h-pair, g, b), 128 threads = 2 rows x 64 lanes, 2 w-positions/thread
__global__ void __launch_bounds__(128) k_offsets(const float* __restrict__ tm_w,
                                                 const float* __restrict__ tm_b) {
    __shared__ float ws[6*9*16];   // ws[(a*9+t)*16 + c]
    const int g = blockIdx.y, b = blockIdx.z;
    const int tid = threadIdx.x;
    for (int i = tid; i < 864; i += 128) {
        int a = i / 144, rem = i - a*144, t = rem >> 4, c = rem & 15;
        int ch = (a >= 3 ? 51 : 0) + (a % 3) * 17 + g;   // i*3G + j*G + g
        ws[i] = tm_w[((size_t)ch*16 + c)*9 + t];
    }
    __syncthreads();
    const int hr = tid >> 6, lane = tid & 63;
    const int h = blockIdx.x * 2 + hr;

    float aff0[6], aff1[6];
    #pragma unroll
    for (int a = 0; a < 6; a++) { aff0[a] = 0.f; aff1[a] = 0.f; }

    #pragma unroll
    for (int a = 0; a < 6; a++) {
        const int ch = (a >= 3 ? 51 : 0) + (a % 3) * 17 + g;
        const int cg = ch / 6;     // conv group of this output channel (NOT g!)
        const float4* xb = reinterpret_cast<const float4*>(g_xT)
                         + (size_t)(b*G_ + cg) * HW_ * 4;
        #pragma unroll 1
        for (int t = 0; t < 9; t++) {
            const int yy  = h + t/3 - 1;
            const int xx0 = lane + t%3 - 1;
            const int xx1 = xx0 + 64;
            const bool yok = ((unsigned)yy < H_);
            const bool ok0 = yok && ((unsigned)xx0 < W_);
            const bool ok1 = yok && ((unsigned)xx1 < W_);
            const float4* v0 = xb + ((size_t)yy*W_ + xx0)*4;
            const float4* v1 = xb + ((size_t)yy*W_ + xx1)*4;
            const float* wr = &ws[(a*9 + t)*16];
            #pragma unroll
            for (int j = 0; j < 4; j++) {
                float4 q0 = ok0 ? v0[j] : make_float4(0.f,0.f,0.f,0.f);
                float4 q1 = ok1 ? v1[j] : make_float4(0.f,0.f,0.f,0.f);
                float w0 = wr[j*4+0], w1 = wr[j*4+1], w2 = wr[j*4+2], w3 = wr[j*4+3];
                aff0[a] = fmaf(q0.x, w0, aff0[a]);
                aff0[a] = fmaf(q0.y, w1, aff0[a]);
                aff0[a] = fmaf(q0.z, w2, aff0[a]);
                aff0[a] = fmaf(q0.w, w3, aff0[a]);
                aff1[a] = fmaf(q1.x, w0, aff1[a]);
                aff1[a] = fmaf(q1.y, w1, aff1[a]);
                aff1[a] = fmaf(q1.z, w2, aff1[a]);
                aff1[a] = fmaf(q1.w, w3, aff1[a]);
            }
        }
        float bias = tm_b[ch];
        aff0[a] += bias; aff1[a] += bias;
    }

    // off rows: rowY[t] = a0*KY[t]+a1*KX[t]+a2 ; rowX[t] = a3*KY[t]+a4*KX[t]+a5
    // flat = [rowY(0..8), rowX(0..8)]; stored slot j holds flat[j]
    float* ob0 = g_off + (size_t)(b*G_ + g)*18*HW_ + h*W_ + lane;
    #pragma unroll
    for (int j = 0; j < 18; j++) {
        int t  = (j < 9) ? j : j - 9;
        float ky = (float)(t/3 - 1), kx = (float)(t%3 - 1);
        float f0, f1;
        if (j < 9) {
            f0 = fmaf(aff0[0], ky, fmaf(aff0[1], kx, aff0[2]));
            f1 = fmaf(aff1[0], ky, fmaf(aff1[1], kx, aff1[2]));
        } else {
            f0 = fmaf(aff0[3], ky, fmaf(aff0[4], kx, aff0[5]));
            f1 = fmaf(aff1[3], ky, fmaf(aff1[4], kx, aff1[5]));
        }
        ob0[(size_t)j*HW_]      = f0;
        ob0[(size_t)j*HW_ + 64] = f1;
    }
}

// ---------------- K2: deformable conv ----------------
__device__ __forceinline__ void corner_acc(float* samp, const float4* xb,
                                           int y, int x, float wgt) {
    if ((unsigned)y < H_ && (unsigned)x < W_) {
        const float4* v = xb + ((size_t)y*W_ + x)*4;
        float4 q0 = v[0], q1 = v[1], q2 = v[2], q3 = v[3];
        samp[0]  = fmaf(wgt, q0.x, samp[0]);
        samp[1]  = fmaf(wgt, q0.y, samp[1]);
        samp[2]  = fmaf(wgt, q0.z, samp[2]);
        samp[3]  = fmaf(wgt, q0.w, samp[3]);
        samp[4]  = fmaf(wgt, q1.x, samp[4]);
        samp[5]  = fmaf(wgt, q1.y, samp[5]);
        samp[6]  = fmaf(wgt, q1.z, samp[6]);
        samp[7]  = fmaf(wgt, q1.w, samp[7]);
        samp[8]  = fmaf(wgt, q2.x, samp[8]);
        samp[9]  = fmaf(wgt, q2.y, samp[9]);
        samp[10] = fmaf(wgt, q2.z, samp[10]);
        samp[11] = fmaf(wgt, q2.w, samp[11]);
        samp[12] = fmaf(wgt, q3.x, samp[12]);
        samp[13] = fmaf(wgt, q3.y, samp[13]);
        samp[14] = fmaf(wgt, q3.z, samp[14]);
        samp[15] = fmaf(wgt, q3.w, samp[15]);
    }
}

__device__ __forceinline__ void sample_tap(float* samp, const float4* xb,
                                           const float* offb, int h, int w, int k) {
    float dy = offb[(size_t)(2*k)  *HW_ + w];
    float dx = offb[(size_t)(2*k+1)*HW_ + w];
    float py = (float)(h + k/3 - 1) + dy;
    float px = (float)(w + k%3 - 1) + dx;
    float y0f = floorf(py), x0f = floorf(px);
    float wy = py - y0f, wx = px - x0f;
    int y0 = (int)y0f, x0 = (int)x0f;
    float w00 = (1.f - wy) * (1.f - wx);
    float w01 = (1.f - wy) * wx;
    float w10 = wy * (1.f - wx);
    float w11 = wy * wx;
    corner_acc(samp, xb, y0,   x0,   w00);
    corner_acc(samp, xb, y0,   x0+1, w01);
    corner_acc(samp, xb, y0+1, x0,   w10);
    corner_acc(samp, xb, y0+1, x0+1, w11);
}

__global__ void __launch_bounds__(128) k_deform(const float* __restrict__ dc_w) {
    __shared__ float ws[9*16*16];  // ws[k*256 + c*16 + o]
    const int g = blockIdx.y, b = blockIdx.z;
    const int tid = threadIdx.x;
    for (int i = tid; i < 2304; i += 128) {
        int k = i >> 8, rem = i & 255, c = rem >> 4, o = rem & 15;
        ws[i] = dc_w[(((size_t)g*16 + o)*16 + c)*9 + k];
    }
    __syncthreads();
    const int hr = tid >> 6, lane = tid & 63;
    const int h  = blockIdx.x * 2 + hr;
    const int bg = b*G_ + g;
    const float4* xb = reinterpret_cast<const float4*>(g_xT) + (size_t)bg * HW_ * 4;
    const float* offb = g_off + (size_t)bg*18*HW_ + h*W_;

    float acc0[16], acc1[16];
    #pragma unroll
    for (int o = 0; o < 16; o++) { acc0[o] = 0.f; acc1[o] = 0.f; }

    #pragma unroll 1
    for (int k = 0; k < 9; k++) {
        float samp0[16], samp1[16];
        #pragma unroll
        for (int c = 0; c < 16; c++) { samp0[c] = 0.f; samp1[c] = 0.f; }
        sample_tap(samp0, xb, offb, h, lane,      k);
        sample_tap(samp1, xb, offb, h, lane + 64, k);
        const float* wk = &ws[k*256];
        #pragma unroll
        for (int c = 0; c < 16; c++) {
            float s0 = samp0[c], s1 = samp1[c];
            #pragma unroll
            for (int o = 0; o < 16; o++) {
                float wt = wk[c*16 + o];
                acc0[o] = fmaf(s0, wt, acc0[o]);
                acc1[o] = fmaf(s1, wt, acc1[o]);
            }
        }
    }
    float* outp = g_conv + ((size_t)b*C_ + g*16)*HW_ + h*W_ + lane;
    #pragma unroll
    for (int o = 0; o < 16; o++) {
        outp[(size_t)o*HW_]      = acc0[o];
        outp[(size_t)o*HW_ + 64] = acc1[o];
    }
}

// ---------------- K3: per-channel BN statistics ----------------
__global__ void k_stats() {
    const int c = blockIdx.x;
    float s = 0.f, s2 = 0.f;
    for (int i = threadIdx.x; i < B_*HW_; i += 256) {
        int b = i >> 14, r = i & (HW_ - 1);
        float v = g_conv[((size_t)b*C_ + c)*HW_ + r];
        s  += v;
        s2 = fmaf(v, v, s2);
    }
    __shared__ float sh[512];
    sh[threadIdx.x] = s;
    sh[256 + threadIdx.x] = s2;
    __syncthreads();
    for (int st = 128; st > 0; st >>= 1) {
        if (threadIdx.x < st) {
            sh[threadIdx.x]       += sh[threadIdx.x + st];
            sh[256 + threadIdx.x] += sh[256 + threadIdx.x + st];
        }
        __syncthreads();
    }
    if (threadIdx.x == 0) {
        const float invN = 1.f / (float)(B_*HW_);
        float mean = sh[0] * invN;
        float var  = sh[256] * invN - mean * mean;
        g_mean[c] = mean;
        g_istd[c] = rsqrtf(var + 1e-5f);
    }
}

// ---------------- K4: BN apply + residual + ReLU ----------------
__global__ void k_final(const float* __restrict__ x, const float* __restrict__ gamma,
                        const float* __restrict__ beta, float* __restrict__ out) {
    int i = blockIdx.x * blockDim.x + threadIdx.x;
    const int total4 = B_*C_*HW_/4;
    if (i >= total4) return;
    int c = (i >> 12) % C_;        // HW/4 = 4096
    float sc = g_istd[c] * gamma[c];
    float sh = beta[c] - g_mean[c] * sc;
    float4 v  = reinterpret_cast<const float4*>(g_conv)[i];
    float4 xv = reinterpret_cast<const float4*>(x)[i];
    float4 r;
    r.x = fmaxf(fmaf(v.x, sc, sh) + xv.x, 0.f);
    r.y = fmaxf(fmaf(v.y, sc, sh) + xv.y, 0.f);
    r.z = fmaxf(fmaf(v.z, sc, sh) + xv.z, 0.f);
    r.w = fmaxf(fmaf(v.w, sc, sh) + xv.w, 0.f);
    reinterpret_cast<float4*>(out)[i] = r;
}

// ---------------- launch ----------------
extern "C" void kernel_launch(void* const* d_in, const int* in_sizes, int n_in,
                              void* d_out, int out_size) {
    const float* x     = (const float*)d_in[0];
    const float* tm_w  = (const float*)d_in[1];
    const float* tm_b  = (const float*)d_in[2];
    const float* dc_w  = (const float*)d_in[3];
    const float* gamma = (const float*)d_in[4];
    const float* beta  = (const float*)d_in[5];
    float* out = (float*)d_out;

    k_transpose<<<(B_*G_*HW_*4 + 255)/256, 256>>>(x);
    dim3 grid(H_/2, G_, B_);
    k_offsets<<<grid, 128>>>(tm_w, tm_b);
    k_deform<<<grid, 128>>>(dc_w);
    k_stats<<<C_, 256>>>();
    k_final<<<(B_*C_*HW_/4 + 255)/256, 256>>>(x, gamma, beta, out);
}

// round 2
// speedup vs baseline: 1.2557x; 1.2557x over previous
#include <cuda_runtime.h>

#define B_  2
#define C_  272
#define H_  128
#define W_  128
#define G_  17
#define CG_ 16
#define HW_ (H_*W_)

// ---------------- scratch (device globals; no allocation) ----------------
__device__ __align__(16) float g_xT[B_*G_*HW_*CG_];   // (b,g,pos,c16)
__device__ __align__(16) float g_off[B_*G_*18*HW_];   // (b,g, slot18, pos)
__device__ __align__(16) float g_conv[B_*C_*HW_];     // (B,C,H,W)
__device__ float g_mean[C_];
__device__ float g_istd[C_];

// ---------------- packed f32x2 helpers ----------------
__device__ __forceinline__ unsigned long long pack2(float lo, float hi) {
    unsigned long long r;
    asm("mov.b64 %0, {%1,%2};" : "=l"(r) : "f"(lo), "f"(hi));
    return r;
}
__device__ __forceinline__ float2 unpack2(unsigned long long v) {
    float2 r;
    asm("mov.b64 {%0,%1}, %2;" : "=f"(r.x), "=f"(r.y) : "l"(v));
    return r;
}
__device__ __forceinline__ void fma2(unsigned long long& d,
                                     unsigned long long a, unsigned long long b) {
    asm("fma.rn.f32x2 %0, %1, %2, %0;" : "+l"(d) : "l"(a), "l"(b));
}

// ---------------- K0: transpose x (B,C,H,W) -> (b,g,pos,c16), shared tile ----
__global__ void __launch_bounds__(256) k_transpose(const float* __restrict__ x) {
    __shared__ float sh[16 * 257];
    const int bg   = blockIdx.y;            // 0..33
    const int base = blockIdx.x * 256;      // position base
    const float* src = x + (size_t)bg * 16 * HW_ + base;
    #pragma unroll
    for (int c = 0; c < 16; c++)
        sh[c * 257 + threadIdx.x] = src[(size_t)c * HW_ + threadIdx.x];
    __syncthreads();
    float4* dst = reinterpret_cast<float4*>(g_xT) + ((size_t)bg * HW_ + base) * 4;
    #pragma unroll
    for (int it = 0; it < 4; it++) {
        int idx = it * 256 + threadIdx.x;
        int p = idx >> 2, q = idx & 3;
        float4 v;
        v.x = sh[(4*q + 0) * 257 + p];
        v.y = sh[(4*q + 1) * 257 + p];
        v.z = sh[(4*q + 2) * 257 + p];
        v.w = sh[(4*q + 3) * 257 + p];
        dst[idx] = v;
    }
}

// ---------------- K1: offset-transform conv + affine->offset ----------------
// block: 256 thr = 64 positions x 4 channel-quads; grid (HW/64, G, B)
__global__ void __launch_bounds__(256) k_offsets(const float* __restrict__ tm_w,
                                                 const float* __restrict__ tm_b) {
    __shared__ __align__(16) float wsa[6*9*16];   // [(a*9+t)*16 + c]
    const int g = blockIdx.y, b = blockIdx.z;
    const int tid = threadIdx.x;
    for (int i = tid; i < 864; i += 256) {
        int a = i / 144, rem = i - a*144, t = rem >> 4, c = rem & 15;
        int ch = (a >= 3 ? 51 : 0) + (a % 3) * 17 + g;   // i*3G + j*G + g
        wsa[i] = tm_w[((size_t)ch*16 + c)*9 + t];
    }
    __syncthreads();

    const int posb = tid >> 2, q = tid & 3;
    const int pos = blockIdx.x * 64 + posb;
    const int h = pos >> 7, w = pos & (W_ - 1);

    unsigned long long acc2[6];
    #pragma unroll
    for (int a = 0; a < 6; a++) acc2[a] = 0ULL;

    int chs[6];
    #pragma unroll
    for (int a = 0; a < 6; a++) {
        const int ch = (a >= 3 ? 51 : 0) + (a % 3) * 17 + g;
        chs[a] = ch;
        const int cg = ch / 6;   // conv group of this output channel (NOT g)
        const ulonglong2* xb = reinterpret_cast<const ulonglong2*>(g_xT)
                             + (size_t)(b*G_ + cg) * HW_ * 4 + q;
        #pragma unroll
        for (int t = 0; t < 9; t++) {
            const int yy = h + t/3 - 1;
            const int xx = w + t%3 - 1;
            ulonglong2 v;
            if ((unsigned)yy < H_ && (unsigned)xx < W_)
                v = xb[(size_t)(yy*W_ + xx) * 4];
            else { v.x = 0ULL; v.y = 0ULL; }
            ulonglong2 wv = *reinterpret_cast<const ulonglong2*>(&wsa[(a*9 + t)*16 + 4*q]);
            fma2(acc2[a], v.x, wv.x);
            fma2(acc2[a], v.y, wv.y);
        }
    }

    float aff[6];
    #pragma unroll
    for (int a = 0; a < 6; a++) {
        float2 p = unpack2(acc2[a]);
        float v = p.x + p.y;
        v += __shfl_xor_sync(0xffffffffu, v, 1);
        v += __shfl_xor_sync(0xffffffffu, v, 2);
        aff[a] = v + tm_b[chs[a]];
    }

    // slot j: j<9 -> rowY[j], j>=9 -> rowX[j-9]
    float* ob = g_off + (size_t)(b*G_ + g) * 18 * HW_ + pos;
    #pragma unroll
    for (int j = 0; j < 18; j++) {
        int t = (j < 9) ? j : j - 9;
        float ky = (float)(t/3 - 1), kx = (float)(t%3 - 1);
        float f = (j < 9)
            ? fmaf(aff[0], ky, fmaf(aff[1], kx, aff[2]))
            : fmaf(aff[3], ky, fmaf(aff[4], kx, aff[5]));
        if ((j & 3) == q) ob[(size_t)j * HW_] = f;
    }
}

// ---------------- K2: deformable conv ----------------
// block: 256 thr = 64 positions x 4 channel-quads; grid (HW/64, G, B)
__global__ void __launch_bounds__(256) k_deform(const float* __restrict__ dc_w) {
    __shared__ __align__(16) float ws[9*16*16];  // [(k*16+o)*16 + c]
    const int g = blockIdx.y, b = blockIdx.z;
    const int tid = threadIdx.x;
    for (int i = tid; i < 2304; i += 256) {
        int k = i >> 8, o = (i >> 4) & 15, c = i & 15;
        ws[i] = dc_w[(((size_t)g*16 + o)*16 + c)*9 + k];
    }
    __syncthreads();

    const int posb = tid >> 2, q = tid & 3;
    const int pos = blockIdx.x * 64 + posb;
    const int h = pos >> 7, w = pos & (W_ - 1);
    const int bg = b*G_ + g;
    const ulonglong2* xb = reinterpret_cast<const ulonglong2*>(g_xT)
                         + (size_t)bg * HW_ * 4 + q;
    const float* offb = g_off + (size_t)bg * 18 * HW_ + pos;

    unsigned long long acc2[16];
    #pragma unroll
    for (int o = 0; o < 16; o++) acc2[o] = 0ULL;

    #pragma unroll 1
    for (int k = 0; k < 9; k++) {
        float dy = offb[(size_t)(2*k)   * HW_];
        float dx = offb[(size_t)(2*k+1) * HW_];
        float py = (float)(h + k/3 - 1) + dy;
        float px = (float)(w + k%3 - 1) + dx;
        float y0f = floorf(py), x0f = floorf(px);
        float wy = py - y0f, wx = px - x0f;
        int y0 = (int)y0f, x0 = (int)x0f;
        float w00 = (1.f - wy) * (1.f - wx);
        float w01 = (1.f - wy) * wx;
        float w10 = wy * (1.f - wx);
        float w11 = wy * wx;

        unsigned long long s0 = 0ULL, s1 = 0ULL;   // samp[4q..4q+1], [4q+2..4q+3]
        {
            if ((unsigned)y0 < H_ && (unsigned)x0 < W_) {
                ulonglong2 v = xb[(size_t)(y0*W_ + x0) * 4];
                unsigned long long wp = pack2(w00, w00);
                fma2(s0, wp, v.x); fma2(s1, wp, v.y);
            }
            if ((unsigned)y0 < H_ && (unsigned)(x0+1) < W_) {
                ulonglong2 v = xb[(size_t)(y0*W_ + x0 + 1) * 4];
                unsigned long long wp = pack2(w01, w01);
                fma2(s0, wp, v.x); fma2(s1, wp, v.y);
            }
            if ((unsigned)(y0+1) < H_ && (unsigned)x0 < W_) {
                ulonglong2 v = xb[(size_t)((y0+1)*W_ + x0) * 4];
                unsigned long long wp = pack2(w10, w10);
                fma2(s0, wp, v.x); fma2(s1, wp, v.y);
            }
            if ((unsigned)(y0+1) < H_ && (unsigned)(x0+1) < W_) {
                ulonglong2 v = xb[(size_t)((y0+1)*W_ + x0 + 1) * 4];
                unsigned long long wp = pack2(w11, w11);
                fma2(s0, wp, v.x); fma2(s1, wp, v.y);
            }
        }
        // GEMM: acc[o] += samp[c] * w[c][o] over this thread's 4 channels
        const float* wk = ws + k*256 + 4*q;
        #pragma unroll
        for (int o = 0; o < 16; o++) {
            ulonglong2 wv = *reinterpret_cast<const ulonglong2*>(wk + o*16);
            fma2(acc2[o], s0, wv.x);
            fma2(acc2[o], s1, wv.y);
        }
    }

    float* outp = g_conv + ((size_t)b*C_ + g*16) * HW_ + pos;
    #pragma unroll
    for (int o = 0; o < 16; o++) {
        float2 p = unpack2(acc2[o]);
        float a = p.x + p.y;
        a += __shfl_xor_sync(0xffffffffu, a, 1);
        a += __shfl_xor_sync(0xffffffffu, a, 2);
        if ((o >> 2) == q) outp[(size_t)o * HW_] = a;
    }
}

// ---------------- K3: per-channel BN statistics ----------------
__global__ void k_stats() {
    const int c = blockIdx.x;
    float s = 0.f, s2 = 0.f;
    for (int i = threadIdx.x; i < B_*HW_; i += 256) {
        int b = i >> 14, r = i & (HW_ - 1 + (HW_ - HW_)); // i & (HW_-1)
        r = i & (HW_ - 1);
        float v = g_conv[((size_t)b*C_ + c)*HW_ + r];
        s  += v;
        s2 = fmaf(v, v, s2);
    }
    __shared__ float sh[512];
    sh[threadIdx.x] = s;
    sh[256 + threadIdx.x] = s2;
    __syncthreads();
    for (int st = 128; st > 0; st >>= 1) {
        if (threadIdx.x < st) {
            sh[threadIdx.x]       += sh[threadIdx.x + st];
            sh[256 + threadIdx.x] += sh[256 + threadIdx.x + st];
        }
        __syncthreads();
    }
    if (threadIdx.x == 0) {
        const float invN = 1.f / (float)(B_*HW_);
        float mean = sh[0] * invN;
        float var  = sh[256] * invN - mean * mean;
        g_mean[c] = mean;
        g_istd[c] = rsqrtf(var + 1e-5f);
    }
}

// ---------------- K4: BN apply + residual + ReLU ----------------
__global__ void k_final(const float* __restrict__ x, const float* __restrict__ gamma,
                        const float* __restrict__ beta, float* __restrict__ out) {
    int i = blockIdx.x * blockDim.x + threadIdx.x;
    const int total4 = B_*C_*HW_/4;
    if (i >= total4) return;
    int c = (i >> 12) % C_;
    float sc = g_istd[c] * gamma[c];
    float sh = beta[c] - g_mean[c] * sc;
    float4 v  = reinterpret_cast<const float4*>(g_conv)[i];
    float4 xv = reinterpret_cast<const float4*>(x)[i];
    float4 r;
    r.x = fmaxf(fmaf(v.x, sc, sh) + xv.x, 0.f);
    r.y = fmaxf(fmaf(v.y, sc, sh) + xv.y, 0.f);
    r.z = fmaxf(fmaf(v.z, sc, sh) + xv.z, 0.f);
    r.w = fmaxf(fmaf(v.w, sc, sh) + xv.w, 0.f);
    reinterpret_cast<float4*>(out)[i] = r;
}

// ---------------- launch ----------------
extern "C" void kernel_launch(void* const* d_in, const int* in_sizes, int n_in,
                              void* d_out, int out_size) {
    const float* x     = (const float*)d_in[0];
    const float* tm_w  = (const float*)d_in[1];
    const float* tm_b  = (const float*)d_in[2];
    const float* dc_w  = (const float*)d_in[3];
    const float* gamma = (const float*)d_in[4];
    const float* beta  = (const float*)d_in[5];
    float* out = (float*)d_out;

    k_transpose<<<dim3(HW_/256, B_*G_), 256>>>(x);
    dim3 grid(HW_/64, G_, B_);
    k_offsets<<<grid, 256>>>(tm_w, tm_b);
    k_deform<<<grid, 256>>>(dc_w);
    k_stats<<<C_, 256>>>();
    k_final<<<(B_*C_*HW_/4 + 255)/256, 256>>>(x, gamma, beta, out);
}